// round 2
// baseline (speedup 1.0000x reference)
#include <cuda_runtime.h>

// Problem constants
#define BATCH 16
#define SEQ   100
#define DIM   8192
#define PDIM  100
#define TPAD  (SEQ + 2)          // 102 padded rows per batch
#define M_ROWS (BATCH * TPAD)    // 1632
#define N_COLS (3 * PDIM)        // 300  (q | k | v)

// GEMM tiling
#define KS 4                     // split-K factor
#define KSPLIT (DIM / KS)        // 2048
#define BM 64
#define BN 64
#define BK 16

// Scratch for split-K partial projections: 4 * 1632 * 300 floats = 7.84 MB
__device__ float g_Y[KS][M_ROWS * N_COLS];

// ---------------------------------------------------------------------------
// Kernel 1: projection GEMM  Y[ks] = padded[:, krange] @ Wcat[krange, :]
//   A is virtual: row r -> (fwd | x | bwd) depending on t = r % TPAD
//   B is virtual: col n -> wq/wk/wv column (n % 100)
// ---------------------------------------------------------------------------
__global__ __launch_bounds__(256, 4)
void proj_gemm(const float* __restrict__ x,  const float* __restrict__ wq,
               const float* __restrict__ wk, const float* __restrict__ wv,
               const float* __restrict__ fwd, const float* __restrict__ bwd)
{
    __shared__ float As[BK][BM];
    __shared__ float Bs[BK][BN];

    const int tid = threadIdx.x;
    const int n0 = blockIdx.x * BN;
    const int m0 = blockIdx.y * BM;
    const int kbase0 = blockIdx.z * KSPLIT;

    // ---- A tile load mapping: each thread owns 1 row, 4 consecutive k (LDG.128)
    const int a_m = tid & 63;          // 0..63
    const int a_k = (tid >> 6) * 4;    // 0,4,8,12
    const int row = m0 + a_m;
    const bool arow_valid = (row < M_ROWS);
    const float* aptr;
    {
        int r = arow_valid ? row : 0;
        int b = r / TPAD;
        int t = r - b * TPAD;
        aptr = (t == 0)        ? (fwd + (size_t)b * DIM)
             : (t == TPAD - 1) ? (bwd + (size_t)b * DIM)
             :                   (x + ((size_t)b * SEQ + (t - 1)) * DIM);
    }

    // ---- B tile load mapping: each thread owns 1 k-row, 4 consecutive n (LDG.128)
    const int b_k  = tid >> 4;         // 0..15
    const int b_n4 = (tid & 15) * 4;   // 0..60
    const int ng = n0 + b_n4;
    const bool bcol_valid = (ng + 3 < N_COLS);
    const float* bptr;
    {
        int g = (ng < N_COLS) ? (ng / PDIM) : 0;   // never crosses group boundary (100 % 4 == 0)
        int c = ng - g * PDIM;
        const float* w = (g == 0) ? wq : (g == 1) ? wk : wv;
        bptr = w + c;                  // element (k, c) lives at w[k * PDIM + c]
    }

    float acc[4][4];
#pragma unroll
    for (int i = 0; i < 4; i++)
#pragma unroll
        for (int j = 0; j < 4; j++) acc[i][j] = 0.f;

    const int ty = tid >> 4;   // 0..15 -> m microtile
    const int tx = tid & 15;   // 0..15 -> n microtile

    float4 a_reg, b_reg;
    // prefetch tile 0
    a_reg = arow_valid ? *(const float4*)(aptr + kbase0 + a_k) : make_float4(0,0,0,0);
    b_reg = bcol_valid ? *(const float4*)(bptr + (size_t)(kbase0 + b_k) * PDIM)
                       : make_float4(0,0,0,0);

    const int ntiles = KSPLIT / BK;
    for (int kt = 0; kt < ntiles; ++kt) {
        __syncthreads();
        As[a_k + 0][a_m] = a_reg.x;
        As[a_k + 1][a_m] = a_reg.y;
        As[a_k + 2][a_m] = a_reg.z;
        As[a_k + 3][a_m] = a_reg.w;
        *(float4*)&Bs[b_k][b_n4] = b_reg;
        __syncthreads();

        // prefetch next tile (hides GMEM latency behind the 256-FFMA compute block)
        if (kt + 1 < ntiles) {
            int kk = kbase0 + (kt + 1) * BK;
            a_reg = arow_valid ? *(const float4*)(aptr + kk + a_k) : make_float4(0,0,0,0);
            b_reg = bcol_valid ? *(const float4*)(bptr + (size_t)(kk + b_k) * PDIM)
                               : make_float4(0,0,0,0);
        }

#pragma unroll
        for (int k = 0; k < BK; k++) {
            float4 af = *(const float4*)&As[k][ty * 4];
            float4 bf = *(const float4*)&Bs[k][tx * 4];
            float av[4] = {af.x, af.y, af.z, af.w};
            float bv[4] = {bf.x, bf.y, bf.z, bf.w};
#pragma unroll
            for (int i = 0; i < 4; i++)
#pragma unroll
                for (int j = 0; j < 4; j++)
                    acc[i][j] += av[i] * bv[j];
        }
    }

    // write partials
    float* out = g_Y[blockIdx.z];
#pragma unroll
    for (int i = 0; i < 4; i++) {
        int r = m0 + ty * 4 + i;
        if (r >= M_ROWS) continue;
#pragma unroll
        for (int j = 0; j < 4; j++) {
            int c = n0 + tx * 4 + j;
            if (c < N_COLS) out[(size_t)r * N_COLS + c] = acc[i][j];
        }
    }
}

// ---------------------------------------------------------------------------
// Kernel 2: split-K reduction + 3-tap local attention, only w=1 row kept.
//   out[b,s,:] = sum_u softmax_u(q(s+1) . k(s+u)) * v(s+u)
// ---------------------------------------------------------------------------
__global__ __launch_bounds__(128)
void attn_epilogue(float* __restrict__ out)
{
    __shared__ float sq[PDIM];
    __shared__ float sk[3][PDIM];
    __shared__ float sv[3][PDIM];
    __shared__ float ssc[3];

    const int bs = blockIdx.x;      // b*SEQ + s
    const int b  = bs / SEQ;
    const int s  = bs - b * SEQ;
    const int tid = threadIdx.x;

    const size_t rowbase = (size_t)(b * TPAD + s) * N_COLS;   // padded row s of batch b

    // gather q (center row), k,v (3 rows), summing the KS split partials
    for (int idx = tid; idx < 7 * PDIM; idx += 128) {
        size_t off;
        int u, c;
        if (idx < PDIM) {
            off = rowbase + N_COLS + idx;                        // q of row s+1, cols [0,100)
        } else if (idx < 4 * PDIM) {
            u = (idx - PDIM) / PDIM; c = (idx - PDIM) - u * PDIM;
            off = rowbase + (size_t)u * N_COLS + PDIM + c;       // k cols [100,200)
        } else {
            u = (idx - 4 * PDIM) / PDIM; c = (idx - 4 * PDIM) - u * PDIM;
            off = rowbase + (size_t)u * N_COLS + 2 * PDIM + c;   // v cols [200,300)
        }
        float v = 0.f;
#pragma unroll
        for (int ksi = 0; ksi < KS; ksi++) v += g_Y[ksi][off];
        if (idx < PDIM)          sq[idx] = v;
        else if (idx < 4 * PDIM) sk[(idx - PDIM) / PDIM][(idx - PDIM) % PDIM] = v;
        else                     sv[(idx - 4 * PDIM) / PDIM][(idx - 4 * PDIM) % PDIM] = v;
    }
    __syncthreads();

    // 3 dot products, one per warp
    const int warp = tid >> 5, lane = tid & 31;
    if (warp < 3) {
        float p = 0.f;
        for (int c = lane; c < PDIM; c += 32) p += sq[c] * sk[warp][c];
#pragma unroll
        for (int o = 16; o; o >>= 1) p += __shfl_xor_sync(0xffffffffu, p, o);
        if (lane == 0) ssc[warp] = p;
    }
    __syncthreads();

    const float s0 = ssc[0], s1 = ssc[1], s2 = ssc[2];
    const float mx = fmaxf(s0, fmaxf(s1, s2));
    float e0 = expf(s0 - mx), e1 = expf(s1 - mx), e2 = expf(s2 - mx);
    const float inv = 1.f / (e0 + e1 + e2);
    e0 *= inv; e1 *= inv; e2 *= inv;

    if (tid < PDIM)
        out[(size_t)bs * PDIM + tid] = e0 * sv[0][tid] + e1 * sv[1][tid] + e2 * sv[2][tid];
}

// ---------------------------------------------------------------------------
extern "C" void kernel_launch(void* const* d_in, const int* in_sizes, int n_in,
                              void* d_out, int out_size)
{
    (void)in_sizes; (void)n_in; (void)out_size;
    const float* x   = (const float*)d_in[0];
    const float* wq  = (const float*)d_in[1];
    const float* wk  = (const float*)d_in[2];
    const float* wv  = (const float*)d_in[3];
    const float* fwd = (const float*)d_in[4];
    const float* bwd = (const float*)d_in[5];
    float* out = (float*)d_out;

    dim3 grid((N_COLS + BN - 1) / BN,   // 5
              (M_ROWS + BM - 1) / BM,   // 26
              KS);                      // 4  -> 520 blocks
    proj_gemm<<<grid, 256>>>(x, wq, wk, wv, fwd, bwd);
    attn_epilogue<<<BATCH * SEQ, 128>>>(out);
}

// round 4
// speedup vs baseline: 1.5403x; 1.5403x over previous
#include <cuda_runtime.h>
#include <cuda_bf16.h>
#include <cstdint>

// ---------------- problem constants ----------------
#define BATCH 16
#define SEQ   100
#define DIM   8192
#define PDIM  100
#define TPAD  102
#define M_ROWS 1632
#define N_COLS 300
#define NPAD   320            // padded N (40 x n8 tiles)
#define KSPLITS 8
#define K_PER  (DIM / KSPLITS)    // 1024
#define KC     32                 // k per chunk
#define NCHUNK (K_PER / KC)       // 32

// GEMM tiling
#define BM 128
#define BN 160
#define NTHREADS 512

// ---------------- global scratch ----------------
__device__ float g_Y[KSPLITS][M_ROWS * N_COLS];                 // 15.7 MB
// weights: transposed + bf16-split + chunk-interleaved: [k/32][NPAD][32]
__device__ __nv_bfloat16 g_Bh[(DIM / KC) * NPAD * KC];
__device__ __nv_bfloat16 g_Bl[(DIM / KC) * NPAD * KC];

// ---------------- smem layout ----------------
// pitch = 40 bf16 = 80 B (32 data + 8 pad) -> conflict-free ldmatrix
#define PITCH_B 80
#define ST_AH 0
#define ST_AL (BM * PITCH_B)                 // 10240
#define ST_BH (2 * BM * PITCH_B)             // 20480
#define ST_BL (2 * BM * PITCH_B + BN * PITCH_B)  // 33280
#define STAGE_BYTES (2 * BM * PITCH_B + 2 * BN * PITCH_B)  // 46080
#define SMEM_TOTAL (2 * STAGE_BYTES)         // 92160

// ---------------- helpers ----------------
__device__ __forceinline__ uint32_t smem_u32(const void* p) {
    uint32_t a;
    asm("{ .reg .u64 t; cvta.to.shared.u64 t, %1; cvt.u32.u64 %0, t; }" : "=r"(a) : "l"(p));
    return a;
}

__device__ __forceinline__ void ldmx4(uint32_t (&r)[4], uint32_t addr) {
    asm volatile("ldmatrix.sync.aligned.m8n8.x4.shared.b16 {%0,%1,%2,%3}, [%4];"
                 : "=r"(r[0]), "=r"(r[1]), "=r"(r[2]), "=r"(r[3]) : "r"(addr));
}
__device__ __forceinline__ void ldmx2(uint32_t (&r)[2], uint32_t addr) {
    asm volatile("ldmatrix.sync.aligned.m8n8.x2.shared.b16 {%0,%1}, [%2];"
                 : "=r"(r[0]), "=r"(r[1]) : "r"(addr));
}
__device__ __forceinline__ void mma_bf16(float (&d)[4], const uint32_t (&a)[4],
                                         const uint32_t (&b)[2]) {
    asm volatile("mma.sync.aligned.m16n8k16.row.col.f32.bf16.bf16.f32 "
                 "{%0,%1,%2,%3},{%4,%5,%6,%7},{%8,%9},{%0,%1,%2,%3};"
                 : "+f"(d[0]), "+f"(d[1]), "+f"(d[2]), "+f"(d[3])
                 : "r"(a[0]), "r"(a[1]), "r"(a[2]), "r"(a[3]), "r"(b[0]), "r"(b[1]));
}

// ---------------------------------------------------------------------------
// Pre-pass: transpose + bf16 hi/lo split weights into chunk-interleaved layout
// g_B[(k>>5)][n][k&31];  n: 0-99 wq, 100-199 wk, 200-299 wv, 300-319 zero
// ---------------------------------------------------------------------------
__global__ __launch_bounds__(256)
void conv_w(const float* __restrict__ wq, const float* __restrict__ wk,
            const float* __restrict__ wv)
{
    __shared__ float t[NPAD * 33];
    const int k0 = blockIdx.x * KC;
    const int tid = threadIdx.x;

    for (int idx = tid; idx < 300 * KC; idx += 256) {
        int r = idx / 300, c = idx - r * 300;              // c coalesced
        const float* w = (c < 100) ? wq : (c < 200) ? wk : wv;
        int cc = (c < 100) ? c : (c < 200) ? c - 100 : c - 200;
        t[c * 33 + r] = w[(size_t)(k0 + r) * PDIM + cc];
    }
    for (int idx = tid; idx < 20 * KC; idx += 256)         // zero pad rows
        t[(300 + (idx >> 5)) * 33 + (idx & 31)] = 0.f;
    __syncthreads();

    const size_t base = (size_t)blockIdx.x * (NPAD * KC);
    for (int idx = tid; idx < NPAD * KC; idx += 256) {
        int n = idx >> 5, r = idx & 31;
        float v = t[n * 33 + r];
        __nv_bfloat16 h = __float2bfloat16(v);
        float res = v - __bfloat162float(h);
        g_Bh[base + idx] = h;
        g_Bl[base + idx] = __float2bfloat16(res);
    }
}

// ---------------------------------------------------------------------------
// Projection GEMM via mma.sync bf16, error-compensated (3 products)
// grid = (N tiles = 2, M tiles = 13, KSPLITS = 8), 512 threads
// ---------------------------------------------------------------------------
__global__ __launch_bounds__(NTHREADS, 2)
void proj_mma(const float* __restrict__ x, const float* __restrict__ fwd,
              const float* __restrict__ bwd)
{
    extern __shared__ char smem[];
    const uint32_t sb = smem_u32(smem);
    const int tid  = threadIdx.x;
    const int lane = tid & 31;
    const int wid  = tid >> 5;                 // 0..15
    const int wr   = wid >> 2;                 // warp row 0..3
    const int wc   = wid & 3;                  // warp col 0..3
    const int m_w  = wr * 32;
    const int n_w  = wc * 40;

    const int n0 = blockIdx.x * BN;
    const int m0 = blockIdx.y * BM;
    const int ks = blockIdx.z;
    const int k0 = ks * K_PER;

    // ---- A gmem pointer: thread owns 1 row, 8 consecutive k ----
    const int arow = tid >> 2;                 // 0..127
    const int akq  = (tid & 3) * 8;            // 0,8,16,24
    const float* abase;
    {
        int r = m0 + arow;
        if (r >= M_ROWS) r = M_ROWS - 1;       // clamp (stores are guarded)
        int b = r / TPAD, t = r - b * TPAD;
        abase = (t == 0)        ? fwd + (size_t)b * DIM
              : (t == TPAD - 1) ? bwd + (size_t)b * DIM
              :                   x + ((size_t)b * SEQ + (t - 1)) * DIM;
        abase += k0 + akq;
    }

    // ---- B gmem: chunk-interleaved, fully coalesced ----
    // chunk base elem index: (k0/KC + c) * NPAD*KC + n0*KC; thread reads 8 bf16 at +tid*8
    const size_t bstep = (size_t)NPAD * KC;
    const size_t bbase0 = (size_t)(k0 / KC) * bstep + (size_t)n0 * KC;

    // ---- per-lane ldmatrix address components ----
    const int a_lrow = (lane & 7) + ((lane >> 3) & 1) * 8;   // 0..15
    const int a_lk   = (lane >> 4) * 8;                      // 0 or 8
    const int b_lrow = lane & 7;
    const int b_lk   = ((lane >> 3) & 1) * 8;                // (lanes 0-15 used)

    float acc[2][5][4];
#pragma unroll
    for (int mi = 0; mi < 2; mi++)
#pragma unroll
        for (int ni = 0; ni < 5; ni++)
#pragma unroll
            for (int q = 0; q < 4; q++) acc[mi][ni][q] = 0.f;

    // prefetch registers
    float4 pa0, pa1;
    uint4 pbh0, pbl0, pbh1, pbl1;

    // prefetch chunk 0
    pa0 = *(const float4*)(abase);
    pa1 = *(const float4*)(abase + 4);
    pbh0 = *(const uint4*)(g_Bh + bbase0 + tid * 8);
    pbl0 = *(const uint4*)(g_Bl + bbase0 + tid * 8);
    if (tid < 128) {
        pbh1 = *(const uint4*)(g_Bh + bbase0 + (tid + NTHREADS) * 8);
        pbl1 = *(const uint4*)(g_Bl + bbase0 + (tid + NTHREADS) * 8);
    }

    for (int c = 0; c < NCHUNK; c++) {
        const int s = c & 1;
        char* stp = smem + s * STAGE_BYTES;
        const uint32_t stg = sb + s * STAGE_BYTES;

        // ---- store stage: A fp32 -> hi/lo bf16 ----
        {
            __nv_bfloat162 h0 = __floats2bfloat162_rn(pa0.x, pa0.y);
            __nv_bfloat162 h1 = __floats2bfloat162_rn(pa0.z, pa0.w);
            __nv_bfloat162 h2 = __floats2bfloat162_rn(pa1.x, pa1.y);
            __nv_bfloat162 h3 = __floats2bfloat162_rn(pa1.z, pa1.w);
            float2 f0 = __bfloat1622float2(h0), f1 = __bfloat1622float2(h1);
            float2 f2 = __bfloat1622float2(h2), f3 = __bfloat1622float2(h3);
            __nv_bfloat162 l0 = __floats2bfloat162_rn(pa0.x - f0.x, pa0.y - f0.y);
            __nv_bfloat162 l1 = __floats2bfloat162_rn(pa0.z - f1.x, pa0.w - f1.y);
            __nv_bfloat162 l2 = __floats2bfloat162_rn(pa1.x - f2.x, pa1.y - f2.y);
            __nv_bfloat162 l3 = __floats2bfloat162_rn(pa1.z - f3.x, pa1.w - f3.y);
            uint32_t off = (uint32_t)arow * PITCH_B + (uint32_t)akq * 2;
            *(uint4*)(stp + ST_AH + off) = make_uint4(
                *(uint32_t*)&h0, *(uint32_t*)&h1, *(uint32_t*)&h2, *(uint32_t*)&h3);
            *(uint4*)(stp + ST_AL + off) = make_uint4(
                *(uint32_t*)&l0, *(uint32_t*)&l1, *(uint32_t*)&l2, *(uint32_t*)&l3);
        }
        // ---- store stage: B (already split) ----
        {
            uint32_t off = (uint32_t)(tid >> 2) * PITCH_B + (uint32_t)(tid & 3) * 16;
            *(uint4*)(stp + ST_BH + off) = pbh0;
            *(uint4*)(stp + ST_BL + off) = pbl0;
            if (tid < 128) {
                int idx = tid + NTHREADS;
                uint32_t off1 = (uint32_t)(idx >> 2) * PITCH_B + (uint32_t)(idx & 3) * 16;
                *(uint4*)(stp + ST_BH + off1) = pbh1;
                *(uint4*)(stp + ST_BL + off1) = pbl1;
            }
        }
        __syncthreads();

        // ---- prefetch next chunk ----
        if (c + 1 < NCHUNK) {
            pa0 = *(const float4*)(abase + (c + 1) * KC);
            pa1 = *(const float4*)(abase + (c + 1) * KC + 4);
            size_t bb = bbase0 + (size_t)(c + 1) * bstep;
            pbh0 = *(const uint4*)(g_Bh + bb + tid * 8);
            pbl0 = *(const uint4*)(g_Bl + bb + tid * 8);
            if (tid < 128) {
                pbh1 = *(const uint4*)(g_Bh + bb + (tid + NTHREADS) * 8);
                pbl1 = *(const uint4*)(g_Bl + bb + (tid + NTHREADS) * 8);
            }
        }

        // ---- compute: 2 k16 steps ----
#pragma unroll
        for (int kk = 0; kk < 2; kk++) {
            uint32_t Ah[2][4], Al[2][4];
#pragma unroll
            for (int mi = 0; mi < 2; mi++) {
                uint32_t aoff = (uint32_t)(m_w + mi * 16 + a_lrow) * PITCH_B
                              + (uint32_t)(kk * 16 + a_lk) * 2;
                ldmx4(Ah[mi], stg + ST_AH + aoff);
                ldmx4(Al[mi], stg + ST_AL + aoff);
            }
#pragma unroll
            for (int ni = 0; ni < 5; ni++) {
                uint32_t Bh[2], Bl[2];
                uint32_t boff = (uint32_t)(n_w + ni * 8 + b_lrow) * PITCH_B
                              + (uint32_t)(kk * 16 + b_lk) * 2;
                ldmx2(Bh, stg + ST_BH + boff);
                ldmx2(Bl, stg + ST_BL + boff);
#pragma unroll
                for (int mi = 0; mi < 2; mi++) {
                    mma_bf16(acc[mi][ni], Ah[mi], Bh);
                    mma_bf16(acc[mi][ni], Ah[mi], Bl);
                    mma_bf16(acc[mi][ni], Al[mi], Bh);
                }
            }
        }
        __syncthreads();
    }

    // ---- writeback to split-K scratch ----
    float* dst = g_Y[ks];
#pragma unroll
    for (int mi = 0; mi < 2; mi++) {
        int row0 = m0 + m_w + mi * 16 + (lane >> 2);
#pragma unroll
        for (int ni = 0; ni < 5; ni++) {
            int col = n0 + n_w + ni * 8 + (lane & 3) * 2;
            if (col < N_COLS) {
                if (row0 < M_ROWS)
                    *(float2*)(dst + (size_t)row0 * N_COLS + col) =
                        make_float2(acc[mi][ni][0], acc[mi][ni][1]);
                if (row0 + 8 < M_ROWS)
                    *(float2*)(dst + (size_t)(row0 + 8) * N_COLS + col) =
                        make_float2(acc[mi][ni][2], acc[mi][ni][3]);
            }
        }
    }
}

// ---------------------------------------------------------------------------
// split-K reduce + 3-tap local attention (w=1 row only)
// ---------------------------------------------------------------------------
__global__ __launch_bounds__(128)
void attn_epilogue(float* __restrict__ out)
{
    __shared__ float sq[PDIM];
    __shared__ float sk[3][PDIM];
    __shared__ float sv[3][PDIM];
    __shared__ float ssc[3];

    const int bs = blockIdx.x;
    const int b  = bs / SEQ;
    const int s  = bs - b * SEQ;
    const int tid = threadIdx.x;
    const size_t rowbase = (size_t)(b * TPAD + s) * N_COLS;

    for (int idx = tid; idx < 7 * PDIM; idx += 128) {
        size_t off;
        if (idx < PDIM) {
            off = rowbase + N_COLS + idx;                                  // q(s+1)
        } else if (idx < 4 * PDIM) {
            int u = (idx - PDIM) / PDIM, c = (idx - PDIM) - u * PDIM;
            off = rowbase + (size_t)u * N_COLS + PDIM + c;                 // k
        } else {
            int u = (idx - 4 * PDIM) / PDIM, c = (idx - 4 * PDIM) - u * PDIM;
            off = rowbase + (size_t)u * N_COLS + 2 * PDIM + c;             // v
        }
        float v = 0.f;
#pragma unroll
        for (int ksi = 0; ksi < KSPLITS; ksi++) v += g_Y[ksi][off];
        if (idx < PDIM)          sq[idx] = v;
        else if (idx < 4 * PDIM) sk[(idx - PDIM) / PDIM][(idx - PDIM) % PDIM] = v;
        else                     sv[(idx - 4 * PDIM) / PDIM][(idx - 4 * PDIM) % PDIM] = v;
    }
    __syncthreads();

    const int warp = tid >> 5, lane = tid & 31;
    if (warp < 3) {
        float p = 0.f;
        for (int c = lane; c < PDIM; c += 32) p += sq[c] * sk[warp][c];
#pragma unroll
        for (int o = 16; o; o >>= 1) p += __shfl_xor_sync(0xffffffffu, p, o);
        if (lane == 0) ssc[warp] = p;
    }
    __syncthreads();

    const float s0 = ssc[0], s1 = ssc[1], s2 = ssc[2];
    const float mx = fmaxf(s0, fmaxf(s1, s2));
    float e0 = expf(s0 - mx), e1 = expf(s1 - mx), e2 = expf(s2 - mx);
    const float inv = 1.f / (e0 + e1 + e2);
    e0 *= inv; e1 *= inv; e2 *= inv;

    if (tid < PDIM)
        out[(size_t)bs * PDIM + tid] = e0 * sv[0][tid] + e1 * sv[1][tid] + e2 * sv[2][tid];
}

// ---------------------------------------------------------------------------
extern "C" void kernel_launch(void* const* d_in, const int* in_sizes, int n_in,
                              void* d_out, int out_size)
{
    (void)in_sizes; (void)n_in; (void)out_size;
    const float* x   = (const float*)d_in[0];
    const float* wq  = (const float*)d_in[1];
    const float* wk  = (const float*)d_in[2];
    const float* wv  = (const float*)d_in[3];
    const float* fwd = (const float*)d_in[4];
    const float* bwd = (const float*)d_in[5];
    float* out = (float*)d_out;

    static bool attr_set = false;
    if (!attr_set) {
        cudaFuncSetAttribute(proj_mma, cudaFuncAttributeMaxDynamicSharedMemorySize,
                             SMEM_TOTAL);
        attr_set = true;
    }

    conv_w<<<DIM / KC, 256>>>(wq, wk, wv);
    proj_mma<<<dim3(NPAD / BN, (M_ROWS + BM - 1) / BM, KSPLITS), NTHREADS, SMEM_TOTAL>>>(
        x, fwd, bwd);
    attn_epilogue<<<BATCH * SEQ, 128>>>(out);
}

// round 6
// speedup vs baseline: 3.0810x; 2.0003x over previous
#include <cuda_runtime.h>
#include <cuda_bf16.h>
#include <cstdint>

// ---------------- problem constants ----------------
#define BATCH 16
#define SEQ   100
#define DIM   8192
#define PDIM  100
#define TPAD  102
#define M_ROWS 1632
#define N_COLS 300
#define NPAD   320            // padded N (40 x n8 tiles)
#define KSPLITS 8
#define K_PER  (DIM / KSPLITS)    // 1024
#define KC     32                 // k per chunk
#define NCHUNK (K_PER / KC)       // 32

// GEMM tiling
#define BM 64
#define BN 160
#define NTHREADS 256

// ---------------- global scratch ----------------
__device__ float g_Y[KSPLITS][M_ROWS * N_COLS];                 // 15.7 MB
// weights: transposed + bf16-split + chunk-interleaved: [k/32][NPAD][32]
__device__ __nv_bfloat16 g_Bh[(DIM / KC) * NPAD * KC];
__device__ __nv_bfloat16 g_Bl[(DIM / KC) * NPAD * KC];

// ---------------- smem layout ----------------
// pitch = 40 bf16 = 80 B (32 data + 8 pad) -> conflict-free ldmatrix
#define PITCH_B 80
#define ST_AH 0
#define ST_AL (BM * PITCH_B)                     // 5120
#define ST_BH (2 * BM * PITCH_B)                 // 10240
#define ST_BL (2 * BM * PITCH_B + BN * PITCH_B)  // 23040
#define STAGE_BYTES (2 * BM * PITCH_B + 2 * BN * PITCH_B)  // 35840
#define SMEM_TOTAL (2 * STAGE_BYTES)             // 71680

// ---------------- helpers ----------------
__device__ __forceinline__ uint32_t smem_u32(const void* p) {
    uint32_t a;
    asm("{ .reg .u64 t; cvta.to.shared.u64 t, %1; cvt.u32.u64 %0, t; }" : "=r"(a) : "l"(p));
    return a;
}
__device__ __forceinline__ void ldmx4(uint32_t (&r)[4], uint32_t addr) {
    asm volatile("ldmatrix.sync.aligned.m8n8.x4.shared.b16 {%0,%1,%2,%3}, [%4];"
                 : "=r"(r[0]), "=r"(r[1]), "=r"(r[2]), "=r"(r[3]) : "r"(addr));
}
__device__ __forceinline__ void ldmx2(uint32_t (&r)[2], uint32_t addr) {
    asm volatile("ldmatrix.sync.aligned.m8n8.x2.shared.b16 {%0,%1}, [%2];"
                 : "=r"(r[0]), "=r"(r[1]) : "r"(addr));
}
__device__ __forceinline__ void mma_bf16(float (&d)[4], const uint32_t (&a)[4],
                                         const uint32_t (&b)[2]) {
    asm volatile("mma.sync.aligned.m16n8k16.row.col.f32.bf16.bf16.f32 "
                 "{%0,%1,%2,%3},{%4,%5,%6,%7},{%8,%9},{%0,%1,%2,%3};"
                 : "+f"(d[0]), "+f"(d[1]), "+f"(d[2]), "+f"(d[3])
                 : "r"(a[0]), "r"(a[1]), "r"(a[2]), "r"(a[3]), "r"(b[0]), "r"(b[1]));
}

// ---------------------------------------------------------------------------
// Pre-pass: transpose + bf16 hi/lo split weights, chunk-interleaved layout
// g_B[(k>>5)][n][k&31];  n: 0-99 wq, 100-199 wk, 200-299 wv, 300-319 zero
// grid = (256 k-chunks, 4 n-groups of 80), 128 threads
// ---------------------------------------------------------------------------
__global__ __launch_bounds__(128)
void conv_w(const float* __restrict__ wq, const float* __restrict__ wk,
            const float* __restrict__ wv)
{
    __shared__ float t[80 * 33];
    const int k0 = blockIdx.x * KC;
    const int n0 = blockIdx.y * 80;
    const int tid = threadIdx.x;

    for (int idx = tid; idx < 80 * KC; idx += 128) {
        int r = idx / 80, c = idx - r * 80;               // c coalesced
        int n = n0 + c;
        float v = 0.f;
        if (n < N_COLS) {
            const float* w = (n < 100) ? wq : (n < 200) ? wk : wv;
            int cc = (n < 100) ? n : (n < 200) ? n - 100 : n - 200;
            v = w[(size_t)(k0 + r) * PDIM + cc];
        }
        t[c * 33 + r] = v;
    }
    __syncthreads();

    const size_t base = (size_t)blockIdx.x * (NPAD * KC) + (size_t)n0 * KC;
    for (int idx = tid; idx < 80 * KC; idx += 128) {
        int n = idx >> 5, r = idx & 31;
        float v = t[n * 33 + r];
        __nv_bfloat16 h = __float2bfloat16(v);
        float res = v - __bfloat162float(h);
        g_Bh[base + idx] = h;                              // idx == n*32 + r
        g_Bl[base + idx] = __float2bfloat16(res);
    }
}

// ---------------------------------------------------------------------------
// Projection GEMM via mma.sync bf16, error-compensated (Ah*Bh + Ah*Bl + Al*Bh)
// grid = (2 N-tiles, 26 M-tiles, KSPLITS) = 416 CTAs, 256 threads
// ---------------------------------------------------------------------------
__global__ __launch_bounds__(NTHREADS, 2)
void proj_mma(const float* __restrict__ x, const float* __restrict__ fwd,
              const float* __restrict__ bwd)
{
    extern __shared__ char smem[];
    const uint32_t sb = smem_u32(smem);
    const int tid  = threadIdx.x;
    const int lane = tid & 31;
    const int wid  = tid >> 5;                 // 0..7
    const int wr   = wid >> 2;                 // 0..1
    const int wc   = wid & 3;                  // 0..3
    const int m_w  = wr * 32;
    const int n_w  = wc * 40;

    const int n0 = blockIdx.x * BN;
    const int m0 = blockIdx.y * BM;
    const int ks = blockIdx.z;
    const int k0 = ks * K_PER;

    // ---- A gmem pointer: thread owns 1 row, 8 consecutive k ----
    const int arow = tid >> 2;                 // 0..63
    const int akq  = (tid & 3) * 8;            // 0,8,16,24
    const float* abase;
    {
        int r = m0 + arow;
        if (r >= M_ROWS) r = M_ROWS - 1;       // clamp (stores are guarded)
        int b = r / TPAD, t = r - b * TPAD;
        abase = (t == 0)        ? fwd + (size_t)b * DIM
              : (t == TPAD - 1) ? bwd + (size_t)b * DIM
              :                   x + ((size_t)b * SEQ + (t - 1)) * DIM;
        abase += k0 + akq;
    }

    // ---- B gmem: chunk-interleaved, coalesced 16B loads ----
    // per chunk: BN*KC bf16 = 5120 elems = 640 uint4 per matrix
    const size_t bstep  = (size_t)NPAD * KC;
    const size_t bbase0 = (size_t)(k0 / KC) * bstep + (size_t)n0 * KC;

    // ---- per-lane ldmatrix address components ----
    const int a_lrow = (lane & 7) + ((lane >> 3) & 1) * 8;
    const int a_lk   = (lane >> 4) * 8;
    const int b_lrow = lane & 7;
    const int b_lk   = ((lane >> 3) & 1) * 8;

    float acc[2][5][4];
#pragma unroll
    for (int mi = 0; mi < 2; mi++)
#pragma unroll
        for (int ni = 0; ni < 5; ni++)
#pragma unroll
            for (int q = 0; q < 4; q++) acc[mi][ni][q] = 0.f;

    // prefetch registers
    float4 pa0, pa1;
    uint4 pbh[3], pbl[3];

    // preload chunk 0
    pa0 = *(const float4*)(abase);
    pa1 = *(const float4*)(abase + 4);
#pragma unroll
    for (int j = 0; j < 3; j++) {
        int idx = tid + j * NTHREADS;
        if (idx < 640) {
            pbh[j] = *(const uint4*)(g_Bh + bbase0 + (size_t)idx * 8);
            pbl[j] = *(const uint4*)(g_Bl + bbase0 + (size_t)idx * 8);
        }
    }

    for (int c = 0; c < NCHUNK; c++) {
        const int s = c & 1;
        char* stp = smem + s * STAGE_BYTES;
        const uint32_t stg = sb + s * STAGE_BYTES;

        // ---- store chunk c into stage s ----
        {
            __nv_bfloat162 h0 = __floats2bfloat162_rn(pa0.x, pa0.y);
            __nv_bfloat162 h1 = __floats2bfloat162_rn(pa0.z, pa0.w);
            __nv_bfloat162 h2 = __floats2bfloat162_rn(pa1.x, pa1.y);
            __nv_bfloat162 h3 = __floats2bfloat162_rn(pa1.z, pa1.w);
            float2 f0 = __bfloat1622float2(h0), f1 = __bfloat1622float2(h1);
            float2 f2 = __bfloat1622float2(h2), f3 = __bfloat1622float2(h3);
            __nv_bfloat162 l0 = __floats2bfloat162_rn(pa0.x - f0.x, pa0.y - f0.y);
            __nv_bfloat162 l1 = __floats2bfloat162_rn(pa0.z - f1.x, pa0.w - f1.y);
            __nv_bfloat162 l2 = __floats2bfloat162_rn(pa1.x - f2.x, pa1.y - f2.y);
            __nv_bfloat162 l3 = __floats2bfloat162_rn(pa1.z - f3.x, pa1.w - f3.y);
            uint32_t off = (uint32_t)arow * PITCH_B + (uint32_t)akq * 2;
            *(uint4*)(stp + ST_AH + off) = make_uint4(
                *(uint32_t*)&h0, *(uint32_t*)&h1, *(uint32_t*)&h2, *(uint32_t*)&h3);
            *(uint4*)(stp + ST_AL + off) = make_uint4(
                *(uint32_t*)&l0, *(uint32_t*)&l1, *(uint32_t*)&l2, *(uint32_t*)&l3);
#pragma unroll
            for (int j = 0; j < 3; j++) {
                int idx = tid + j * NTHREADS;
                if (idx < 640) {
                    uint32_t boff = (uint32_t)(idx >> 2) * PITCH_B
                                  + (uint32_t)(idx & 3) * 16;
                    *(uint4*)(stp + ST_BH + boff) = pbh[j];
                    *(uint4*)(stp + ST_BL + boff) = pbl[j];
                }
            }
        }
        __syncthreads();       // single barrier per chunk

        // ---- prefetch chunk c+1 (LDGs in flight during compute) ----
        if (c + 1 < NCHUNK) {
            pa0 = *(const float4*)(abase + (c + 1) * KC);
            pa1 = *(const float4*)(abase + (c + 1) * KC + 4);
            size_t bb = bbase0 + (size_t)(c + 1) * bstep;
#pragma unroll
            for (int j = 0; j < 3; j++) {
                int idx = tid + j * NTHREADS;
                if (idx < 640) {
                    pbh[j] = *(const uint4*)(g_Bh + bb + (size_t)idx * 8);
                    pbl[j] = *(const uint4*)(g_Bl + bb + (size_t)idx * 8);
                }
            }
        }

        // ---- compute stage s: 2 k16 steps ----
#pragma unroll
        for (int kk = 0; kk < 2; kk++) {
            uint32_t Ah[2][4], Al[2][4];
#pragma unroll
            for (int mi = 0; mi < 2; mi++) {
                uint32_t aoff = (uint32_t)(m_w + mi * 16 + a_lrow) * PITCH_B
                              + (uint32_t)(kk * 16 + a_lk) * 2;
                ldmx4(Ah[mi], stg + ST_AH + aoff);
                ldmx4(Al[mi], stg + ST_AL + aoff);
            }
#pragma unroll
            for (int ni = 0; ni < 5; ni++) {
                uint32_t Bh[2], Bl[2];
                uint32_t boff = (uint32_t)(n_w + ni * 8 + b_lrow) * PITCH_B
                              + (uint32_t)(kk * 16 + b_lk) * 2;
                ldmx2(Bh, stg + ST_BH + boff);
                ldmx2(Bl, stg + ST_BL + boff);
#pragma unroll
                for (int mi = 0; mi < 2; mi++) {
                    mma_bf16(acc[mi][ni], Ah[mi], Bh);
                    mma_bf16(acc[mi][ni], Ah[mi], Bl);
                    mma_bf16(acc[mi][ni], Al[mi], Bh);
                }
            }
        }
    }

    // ---- writeback to split-K scratch ----
    float* dst = g_Y[ks];
#pragma unroll
    for (int mi = 0; mi < 2; mi++) {
        int row0 = m0 + m_w + mi * 16 + (lane >> 2);
#pragma unroll
        for (int ni = 0; ni < 5; ni++) {
            int col = n0 + n_w + ni * 8 + (lane & 3) * 2;
            if (col < N_COLS) {
                if (row0 < M_ROWS)
                    *(float2*)(dst + (size_t)row0 * N_COLS + col) =
                        make_float2(acc[mi][ni][0], acc[mi][ni][1]);
                if (row0 + 8 < M_ROWS)
                    *(float2*)(dst + (size_t)(row0 + 8) * N_COLS + col) =
                        make_float2(acc[mi][ni][2], acc[mi][ni][3]);
            }
        }
    }
}

// ---------------------------------------------------------------------------
// split-K reduce + 3-tap local attention (w=1 row only)
// ---------------------------------------------------------------------------
__global__ __launch_bounds__(128)
void attn_epilogue(float* __restrict__ out)
{
    __shared__ float sq[PDIM];
    __shared__ float sk[3][PDIM];
    __shared__ float sv[3][PDIM];
    __shared__ float ssc[3];

    const int bs = blockIdx.x;
    const int b  = bs / SEQ;
    const int s  = bs - b * SEQ;
    const int tid = threadIdx.x;
    const size_t rowbase = (size_t)(b * TPAD + s) * N_COLS;

    for (int idx = tid; idx < 7 * PDIM; idx += 128) {
        size_t off;
        if (idx < PDIM) {
            off = rowbase + N_COLS + idx;                                  // q(s+1)
        } else if (idx < 4 * PDIM) {
            int u = (idx - PDIM) / PDIM, c = (idx - PDIM) - u * PDIM;
            off = rowbase + (size_t)u * N_COLS + PDIM + c;                 // k
        } else {
            int u = (idx - 4 * PDIM) / PDIM, c = (idx - 4 * PDIM) - u * PDIM;
            off = rowbase + (size_t)u * N_COLS + 2 * PDIM + c;             // v
        }
        float v = 0.f;
#pragma unroll
        for (int ksi = 0; ksi < KSPLITS; ksi++) v += g_Y[ksi][off];
        if (idx < PDIM)          sq[idx] = v;
        else if (idx < 4 * PDIM) sk[(idx - PDIM) / PDIM][(idx - PDIM) % PDIM] = v;
        else                     sv[(idx - 4 * PDIM) / PDIM][(idx - 4 * PDIM) % PDIM] = v;
    }
    __syncthreads();

    const int warp = tid >> 5, lane = tid & 31;
    if (warp < 3) {
        float p = 0.f;
        for (int c = lane; c < PDIM; c += 32) p += sq[c] * sk[warp][c];
#pragma unroll
        for (int o = 16; o; o >>= 1) p += __shfl_xor_sync(0xffffffffu, p, o);
        if (lane == 0) ssc[warp] = p;
    }
    __syncthreads();

    const float s0 = ssc[0], s1 = ssc[1], s2 = ssc[2];
    const float mx = fmaxf(s0, fmaxf(s1, s2));
    float e0 = expf(s0 - mx), e1 = expf(s1 - mx), e2 = expf(s2 - mx);
    const float inv = 1.f / (e0 + e1 + e2);
    e0 *= inv; e1 *= inv; e2 *= inv;

    if (tid < PDIM)
        out[(size_t)bs * PDIM + tid] = e0 * sv[0][tid] + e1 * sv[1][tid] + e2 * sv[2][tid];
}

// ---------------------------------------------------------------------------
extern "C" void kernel_launch(void* const* d_in, const int* in_sizes, int n_in,
                              void* d_out, int out_size)
{
    (void)in_sizes; (void)n_in; (void)out_size;
    const float* x   = (const float*)d_in[0];
    const float* wq  = (const float*)d_in[1];
    const float* wk  = (const float*)d_in[2];
    const float* wv  = (const float*)d_in[3];
    const float* fwd = (const float*)d_in[4];
    const float* bwd = (const float*)d_in[5];
    float* out = (float*)d_out;

    static bool attr_set = false;
    if (!attr_set) {
        cudaFuncSetAttribute(proj_mma, cudaFuncAttributeMaxDynamicSharedMemorySize,
                             SMEM_TOTAL);
        attr_set = true;
    }

    conv_w<<<dim3(DIM / KC, 4), 128>>>(wq, wk, wv);
    proj_mma<<<dim3(NPAD / BN, (M_ROWS + BM - 1) / BM, KSPLITS), NTHREADS, SMEM_TOTAL>>>(
        x, fwd, bwd);
    attn_epilogue<<<BATCH * SEQ, 128>>>(out);
}

// round 7
// speedup vs baseline: 3.1983x; 1.0381x over previous
#include <cuda_runtime.h>
#include <cuda_bf16.h>
#include <cstdint>

// ---------------- problem constants ----------------
#define BATCH 16
#define SEQ   100
#define DIM   8192
#define PDIM  100
#define TPAD  102
#define M_ROWS 1632
#define N_COLS 300
#define NPAD   320
#define KSPLITS 16
#define K_PER  (DIM / KSPLITS)    // 512
#define KC     32                 // k per chunk
#define NCHUNK (K_PER / KC)       // 16

// GEMM tiling
#define BM 64
#define BN 160
#define NTHREADS 256
#define NSTAGES 3

// ---------------- global scratch ----------------
__device__ float g_Y[KSPLITS][M_ROWS * N_COLS];            // 31.3 MB
// weights: bf16 hi/lo split, natural layout [k][NPAD] (n: 0-99 wq, 100-199 wk,
// 200-299 wv, 300-319 zero)
__device__ __nv_bfloat16 g_Bh[(size_t)DIM * NPAD];
__device__ __nv_bfloat16 g_Bl[(size_t)DIM * NPAD];

// ---------------- smem layout ----------------
#define PITCH_A 80                    // 32 bf16 + 8 pad
#define PITCH_BK 336                  // 160 bf16 + 8 pad (21 x 16B, odd -> conflict-free trans)
#define ST_AH 0
#define ST_AL (BM * PITCH_A)                         // 5120
#define ST_BH (2 * BM * PITCH_A)                     // 10240
#define ST_BL (2 * BM * PITCH_A + KC * PITCH_BK)     // 20992
#define STAGE_BYTES (2 * BM * PITCH_A + 2 * KC * PITCH_BK)   // 31744
#define SMEM_TOTAL (NSTAGES * STAGE_BYTES)           // 95232

// ---------------- helpers ----------------
__device__ __forceinline__ uint32_t smem_u32(const void* p) {
    uint32_t a;
    asm("{ .reg .u64 t; cvta.to.shared.u64 t, %1; cvt.u32.u64 %0, t; }" : "=r"(a) : "l"(p));
    return a;
}
__device__ __forceinline__ void ldmx4(uint32_t (&r)[4], uint32_t addr) {
    asm volatile("ldmatrix.sync.aligned.m8n8.x4.shared.b16 {%0,%1,%2,%3}, [%4];"
                 : "=r"(r[0]), "=r"(r[1]), "=r"(r[2]), "=r"(r[3]) : "r"(addr));
}
__device__ __forceinline__ void ldmx2t(uint32_t (&r)[2], uint32_t addr) {
    asm volatile("ldmatrix.sync.aligned.m8n8.x2.trans.shared.b16 {%0,%1}, [%2];"
                 : "=r"(r[0]), "=r"(r[1]) : "r"(addr));
}
__device__ __forceinline__ void mma_bf16(float (&d)[4], const uint32_t (&a)[4],
                                         const uint32_t (&b)[2]) {
    asm volatile("mma.sync.aligned.m16n8k16.row.col.f32.bf16.bf16.f32 "
                 "{%0,%1,%2,%3},{%4,%5,%6,%7},{%8,%9},{%0,%1,%2,%3};"
                 : "+f"(d[0]), "+f"(d[1]), "+f"(d[2]), "+f"(d[3])
                 : "r"(a[0]), "r"(a[1]), "r"(a[2]), "r"(a[3]), "r"(b[0]), "r"(b[1]));
}
#define CP16(dst, src) \
    asm volatile("cp.async.cg.shared.global [%0], [%1], 16;" :: "r"(dst), "l"(src))
#define CP_COMMIT() asm volatile("cp.async.commit_group;" ::: "memory")
#define CP_WAIT1()  asm volatile("cp.async.wait_group 1;" ::: "memory")
#define CP_WAIT0()  asm volatile("cp.async.wait_group 0;" ::: "memory")

// ---------------------------------------------------------------------------
// Pre-pass: pure streaming bf16 hi/lo split, no transpose. g_B[k][n].
// ---------------------------------------------------------------------------
__global__ __launch_bounds__(256)
void conv_w(const float* __restrict__ wq, const float* __restrict__ wk,
            const float* __restrict__ wv)
{
    const int stride = gridDim.x * 256;
    for (size_t idx = (size_t)blockIdx.x * 256 + threadIdx.x;
         idx < (size_t)DIM * NPAD; idx += stride) {
        int k = (int)(idx / NPAD), n = (int)(idx - (size_t)k * NPAD);
        float v = 0.f;
        if (n < N_COLS) {
            const float* w = (n < 100) ? wq : (n < 200) ? wk : wv;
            int c = (n < 100) ? n : (n < 200) ? n - 100 : n - 200;
            v = w[(size_t)k * PDIM + c];
        }
        __nv_bfloat16 h = __float2bfloat16(v);
        g_Bh[idx] = h;
        g_Bl[idx] = __float2bfloat16(v - __bfloat162float(h));
    }
}

// ---------------------------------------------------------------------------
// Projection GEMM: mma.sync bf16, error-compensated (Ah*Bh + Ah*Bl + Al*Bh)
// grid = (2 N-tiles, 26 M-tiles, 16 k-splits) = 832 CTAs, 256 threads
// B via cp.async 3-stage; A via reg conversion pipeline. 1 sync/chunk.
// ---------------------------------------------------------------------------
__global__ __launch_bounds__(NTHREADS, 2)
void proj_mma(const float* __restrict__ x, const float* __restrict__ fwd,
              const float* __restrict__ bwd)
{
    extern __shared__ char smem[];
    const uint32_t sb = smem_u32(smem);
    const int tid  = threadIdx.x;
    const int lane = tid & 31;
    const int wid  = tid >> 5;                 // 0..7
    const int m_w  = (wid >> 2) * 32;          // 0,32
    const int n_w  = (wid & 3) * 40;           // 0,40,80,120

    const int n0 = blockIdx.x * BN;
    const int m0 = blockIdx.y * BM;
    const int ks = blockIdx.z;
    const int k0 = ks * K_PER;

    // ---- A gmem pointer: thread owns 1 row, 8 consecutive k ----
    const int arow = tid >> 2;                 // 0..63
    const int akq  = (tid & 3) * 8;            // 0,8,16,24
    const float* abase;
    {
        int r = m0 + arow;
        if (r >= M_ROWS) r = M_ROWS - 1;       // clamp (stores guarded)
        int b = r / TPAD, t = r - b * TPAD;
        abase = (t == 0)        ? fwd + (size_t)b * DIM
              : (t == TPAD - 1) ? bwd + (size_t)b * DIM
              :                   x + ((size_t)b * SEQ + (t - 1)) * DIM;
        abase += k0 + akq;
    }

    // ---- B cp.async mapping: 1280 x 16B per chunk = 5 per thread ----
    // idx -> matrix (hi/lo), r (k-row 0..31), u (16B unit 0..19)
    int b_mat[5], b_r[5], b_u[5];
#pragma unroll
    for (int j = 0; j < 5; j++) {
        int idx = tid + j * NTHREADS;          // 0..1279
        b_mat[j] = idx >= 640;
        int rem = idx - (b_mat[j] ? 640 : 0);
        b_r[j] = rem / 20;
        b_u[j] = rem - b_r[j] * 20;
    }

    // ---- per-lane ldmatrix address components ----
    const int a_lrow = (lane & 7) + ((lane >> 3) & 1) * 8;
    const int a_lk   = (lane >> 4) * 8;
    const int b_lk   = (lane & 7) + ((lane >> 3) & 1) * 8;   // k row within 16 (lanes 0-15)

    float acc[2][5][4];
#pragma unroll
    for (int mi = 0; mi < 2; mi++)
#pragma unroll
        for (int ni = 0; ni < 5; ni++)
#pragma unroll
            for (int q = 0; q < 4; q++) acc[mi][ni][q] = 0.f;

    // ---- helpers for staging ----
    auto stage_B = [&](int c) {
        const uint32_t stg = sb + (c % NSTAGES) * STAGE_BYTES;
        const size_t krow = (size_t)(k0 + c * KC);
#pragma unroll
        for (int j = 0; j < 5; j++) {
            const __nv_bfloat16* g = b_mat[j] ? g_Bl : g_Bh;
            const __nv_bfloat16* src = g + (krow + b_r[j]) * NPAD + n0 + b_u[j] * 8;
            uint32_t dst = stg + (b_mat[j] ? ST_BL : ST_BH)
                         + (uint32_t)b_r[j] * PITCH_BK + (uint32_t)b_u[j] * 16;
            CP16(dst, src);
        }
        CP_COMMIT();
    };

    float4 pa0, pa1;   // A chunk held in regs pending conversion+STS
    auto load_A = [&](int c) {
        pa0 = *(const float4*)(abase + c * KC);
        pa1 = *(const float4*)(abase + c * KC + 4);
    };
    auto store_A = [&](int c) {
        char* stp = smem + (c % NSTAGES) * STAGE_BYTES;
        __nv_bfloat162 h0 = __floats2bfloat162_rn(pa0.x, pa0.y);
        __nv_bfloat162 h1 = __floats2bfloat162_rn(pa0.z, pa0.w);
        __nv_bfloat162 h2 = __floats2bfloat162_rn(pa1.x, pa1.y);
        __nv_bfloat162 h3 = __floats2bfloat162_rn(pa1.z, pa1.w);
        float2 f0 = __bfloat1622float2(h0), f1 = __bfloat1622float2(h1);
        float2 f2 = __bfloat1622float2(h2), f3 = __bfloat1622float2(h3);
        __nv_bfloat162 l0 = __floats2bfloat162_rn(pa0.x - f0.x, pa0.y - f0.y);
        __nv_bfloat162 l1 = __floats2bfloat162_rn(pa0.z - f1.x, pa0.w - f1.y);
        __nv_bfloat162 l2 = __floats2bfloat162_rn(pa1.x - f2.x, pa1.y - f2.y);
        __nv_bfloat162 l3 = __floats2bfloat162_rn(pa1.z - f3.x, pa1.w - f3.y);
        uint32_t off = (uint32_t)arow * PITCH_A + (uint32_t)akq * 2;
        *(uint4*)(stp + ST_AH + off) = make_uint4(
            *(uint32_t*)&h0, *(uint32_t*)&h1, *(uint32_t*)&h2, *(uint32_t*)&h3);
        *(uint4*)(stp + ST_AL + off) = make_uint4(
            *(uint32_t*)&l0, *(uint32_t*)&l1, *(uint32_t*)&l2, *(uint32_t*)&l3);
    };

    // ---- prologue: stages 0 and 1 in flight ----
    load_A(0);
    stage_B(0);
    store_A(0);
    load_A(1);
    stage_B(1);
    store_A(1);
    load_A(2);
    CP_WAIT1();            // B(0) complete
    __syncthreads();       // A(0) + B(0) visible

    for (int c = 0; c < NCHUNK; c++) {
        const uint32_t stg = sb + (c % NSTAGES) * STAGE_BYTES;

        // ---- compute chunk c ----
#pragma unroll
        for (int kk = 0; kk < 2; kk++) {
            uint32_t Ah[2][4], Al[2][4];
#pragma unroll
            for (int mi = 0; mi < 2; mi++) {
                uint32_t aoff = (uint32_t)(m_w + mi * 16 + a_lrow) * PITCH_A
                              + (uint32_t)(kk * 16 + a_lk) * 2;
                ldmx4(Ah[mi], stg + ST_AH + aoff);
                ldmx4(Al[mi], stg + ST_AL + aoff);
            }
            const uint32_t brow = (uint32_t)(kk * 16 + b_lk) * PITCH_BK;
#pragma unroll
            for (int ni = 0; ni < 5; ni++) {
                uint32_t Bh[2], Bl[2];
                uint32_t boff = brow + (uint32_t)(n_w + ni * 8) * 2;
                ldmx2t(Bh, stg + ST_BH + boff);
                ldmx2t(Bl, stg + ST_BL + boff);
#pragma unroll
                for (int mi = 0; mi < 2; mi++) {
                    mma_bf16(acc[mi][ni], Ah[mi], Bh);
                    mma_bf16(acc[mi][ni], Ah[mi], Bl);
                    mma_bf16(acc[mi][ni], Al[mi], Bh);
                }
            }
        }

        // ---- refill stage (c+2)%3 (buffer last used by compute(c-1)) ----
        if (c + 2 < NCHUNK) {
            store_A(c + 2);            // from pa (loaded at iter c-1 / prologue)
            stage_B(c + 2);
            if (c + 3 < NCHUNK) load_A(c + 3);
            CP_WAIT1();                // B(c+1) complete
        } else {
            CP_WAIT0();                // drain
        }
        __syncthreads();               // publish stage c+1; protect reuse
    }

    // ---- writeback to split-K scratch ----
    float* dst = g_Y[ks];
#pragma unroll
    for (int mi = 0; mi < 2; mi++) {
        int row0 = m0 + m_w + mi * 16 + (lane >> 2);
#pragma unroll
        for (int ni = 0; ni < 5; ni++) {
            int col = n0 + n_w + ni * 8 + (lane & 3) * 2;
            if (col < N_COLS) {
                if (row0 < M_ROWS)
                    *(float2*)(dst + (size_t)row0 * N_COLS + col) =
                        make_float2(acc[mi][ni][0], acc[mi][ni][1]);
                if (row0 + 8 < M_ROWS)
                    *(float2*)(dst + (size_t)(row0 + 8) * N_COLS + col) =
                        make_float2(acc[mi][ni][2], acc[mi][ni][3]);
            }
        }
    }
}

// ---------------------------------------------------------------------------
// split-K reduce + 3-tap local attention (w=1 row only)
// ---------------------------------------------------------------------------
__global__ __launch_bounds__(128)
void attn_epilogue(float* __restrict__ out)
{
    __shared__ float sq[PDIM];
    __shared__ float sk[3][PDIM];
    __shared__ float sv[3][PDIM];
    __shared__ float ssc[3];

    const int bs = blockIdx.x;
    const int b  = bs / SEQ;
    const int s  = bs - b * SEQ;
    const int tid = threadIdx.x;
    const size_t rowbase = (size_t)(b * TPAD + s) * N_COLS;

    for (int idx = tid; idx < 7 * PDIM; idx += 128) {
        size_t off;
        if (idx < PDIM) {
            off = rowbase + N_COLS + idx;                                  // q(s+1)
        } else if (idx < 4 * PDIM) {
            int u = (idx - PDIM) / PDIM, c = (idx - PDIM) - u * PDIM;
            off = rowbase + (size_t)u * N_COLS + PDIM + c;                 // k
        } else {
            int u = (idx - 4 * PDIM) / PDIM, c = (idx - 4 * PDIM) - u * PDIM;
            off = rowbase + (size_t)u * N_COLS + 2 * PDIM + c;             // v
        }
        float v = 0.f;
#pragma unroll
        for (int ksi = 0; ksi < KSPLITS; ksi++) v += g_Y[ksi][off];
        if (idx < PDIM)          sq[idx] = v;
        else if (idx < 4 * PDIM) sk[(idx - PDIM) / PDIM][(idx - PDIM) % PDIM] = v;
        else                     sv[(idx - 4 * PDIM) / PDIM][(idx - 4 * PDIM) % PDIM] = v;
    }
    __syncthreads();

    const int warp = tid >> 5, lane = tid & 31;
    if (warp < 3) {
        float p = 0.f;
        for (int c = lane; c < PDIM; c += 32) p += sq[c] * sk[warp][c];
#pragma unroll
        for (int o = 16; o; o >>= 1) p += __shfl_xor_sync(0xffffffffu, p, o);
        if (lane == 0) ssc[warp] = p;
    }
    __syncthreads();

    const float s0 = ssc[0], s1 = ssc[1], s2 = ssc[2];
    const float mx = fmaxf(s0, fmaxf(s1, s2));
    float e0 = expf(s0 - mx), e1 = expf(s1 - mx), e2 = expf(s2 - mx);
    const float inv = 1.f / (e0 + e1 + e2);
    e0 *= inv; e1 *= inv; e2 *= inv;

    if (tid < PDIM)
        out[(size_t)bs * PDIM + tid] = e0 * sv[0][tid] + e1 * sv[1][tid] + e2 * sv[2][tid];
}

// ---------------------------------------------------------------------------
extern "C" void kernel_launch(void* const* d_in, const int* in_sizes, int n_in,
                              void* d_out, int out_size)
{
    (void)in_sizes; (void)n_in; (void)out_size;
    const float* x   = (const float*)d_in[0];
    const float* wq  = (const float*)d_in[1];
    const float* wk  = (const float*)d_in[2];
    const float* wv  = (const float*)d_in[3];
    const float* fwd = (const float*)d_in[4];
    const float* bwd = (const float*)d_in[5];
    float* out = (float*)d_out;

    static bool attr_set = false;
    if (!attr_set) {
        cudaFuncSetAttribute(proj_mma, cudaFuncAttributeMaxDynamicSharedMemorySize,
                             SMEM_TOTAL);
        attr_set = true;
    }

    conv_w<<<2048, 256>>>(wq, wk, wv);
    proj_mma<<<dim3(NPAD / BN, (M_ROWS + BM - 1) / BM, KSPLITS), NTHREADS, SMEM_TOTAL>>>(
        x, fwd, bwd);
    attn_epilogue<<<BATCH * SEQ, 128>>>(out);
}